// round 5
// baseline (speedup 1.0000x reference)
#include <cuda_runtime.h>
#include <math.h>
#include <float.h>

#define B 8
#define H 480
#define W 640
#define HW (H*W)
#define TOPK 500
#define NKP (B*TOPK)
#define CAP 131072

#define KXY_OFF 0
#define DESC_OFF (NKP*2)
#define KPS_OFF (DESC_OFF + NKP*64)
#define DISP_OFF (KPS_OFF + NKP)

// ---------------- device scratch ----------------
__device__ float g_cval[B*CAP];
__device__ int   g_cidx[B*CAP];
__device__ int   g_cnt[B];          // zero-initialized at load; re-zeroed by select
__device__ int   g_topk[NKP];

// ============================================================================
// Fused NMS: 64x32 output tile, radius-10 halo. smem rows 52 x padded width 92.
// Data cols sc in [4,88); guard cols zeroed. SS recomputed as SMK?0:sT.
// ============================================================================
#define PW 92
#define NCH 21   /* chunks cb = 4 + 4k, k=0..20, covering sc [4,88) */

#define F4(A, r, cb)   (*(const float4*)&A[(r)*PW + (cb)])
#define F4W(A, r, cb)  (*(float4*)&A[(r)*PW + (cb)])
#define U32(A, r, cb)  (*(const unsigned*)&A[(r)*PW + (cb)])
#define U32W(A, r, cb) (*(unsigned*)&A[(r)*PW + (cb)])

__device__ __forceinline__ float4 f4max(float4 a, float4 b) {
    return make_float4(fmaxf(a.x,b.x), fmaxf(a.y,b.y), fmaxf(a.z,b.z), fmaxf(a.w,b.w));
}
__device__ __forceinline__ float fmax5(float a, float b, float c, float d, float e) {
    return fmaxf(fmaxf(fmaxf(a, b), fmaxf(c, d)), e);
}
__device__ __forceinline__ float4 ss_ld(const float* sT, const unsigned char* SMK,
                                        int r, int cb) {
    unsigned w = U32(SMK, r, cb);
    float4 t = F4(sT, r, cb);
    t.x = (w & 0xFFu)       ? 0.f : t.x;
    t.y = (w & 0xFF00u)     ? 0.f : t.y;
    t.z = (w & 0xFF0000u)   ? 0.f : t.z;
    t.w = (w & 0xFF000000u) ? 0.f : t.w;
    return t;
}

__global__ __launch_bounds__(512) void nms_kernel(const float* __restrict__ s) {
    __shared__ __align__(16) float sT[52*PW];
    __shared__ __align__(16) float TF[52*PW];
    __shared__ __align__(4) unsigned char M  [52*PW];
    __shared__ __align__(4) unsigned char SMK[52*PW];

    int b = blockIdx.z, tid = threadIdx.x;
    int gx0 = blockIdx.x*64 - 10, gy0 = blockIdx.y*32 - 10;
    const float* sp = s + (size_t)b*HW;

    // zero guard columns of TF and M (sc [0,4) and [88,92))
    if (tid < 52) {
        int r = tid;
        #pragma unroll
        for (int j = 0; j < 4; j++) { TF[r*PW + j] = 0.f; TF[r*PW + 88 + j] = 0.f; }
        ((unsigned*)M)[r*23 + 0] = 0u;
        ((unsigned*)M)[r*23 + 22] = 0u;
    }
    // load tile (guards + OOB = 0)
    for (int i = tid; i < 52*PW; i += 512) {
        int r = i / PW, sc = i - r*PW;
        int gy = gy0 + r, gx = gx0 + sc - 4;
        float v = 0.f;
        if (sc >= 4 && sc < 88 && gy >= 0 && gy < H && gx >= 0 && gx < W)
            v = sp[gy*W + gx];
        sT[i] = v;
    }
    __syncthreads();

#define HWIN(r, cb, o0, o1, o2, o3)                                           \
    float4 L = F4(TF,r,(cb)-4), Md = F4(TF,r,cb), R = F4(TF,r,(cb)+4);        \
    float o0 = fmax5(L.z, L.w, Md.x, Md.y, Md.z);                             \
    float o1 = fmax5(L.w, Md.x, Md.y, Md.z, Md.w);                            \
    float o2 = fmax5(Md.x, Md.y, Md.z, Md.w, R.x);                            \
    float o3 = fmax5(Md.y, Md.z, Md.w, R.x, R.y);

#define OR5(r, x) (U32(M,(r)-2,x)|U32(M,(r)-1,x)|U32(M,r,x)|U32(M,(r)+1,x)|U32(M,(r)+2,x))

    // ---- stage 1 vpass: TF = vmax5(sT), rows [2,50) ----
    for (int i = tid; i < 48*NCH; i += 512) {
        int q = i/NCH, k = i - q*NCH;
        int r = 2+q, cb = 4 + 4*k;
        float4 v = f4max(f4max(F4(sT,r-2,cb), F4(sT,r-1,cb)),
                         f4max(F4(sT,r+1,cb), F4(sT,r+2,cb)));
        F4W(TF,r,cb) = f4max(v, F4(sT,r,cb));
    }
    __syncthreads();
    // ---- stage 1 hpass: M = (sT == hmax5(TF)), rows [2,50) ----
    for (int i = tid; i < 48*NCH; i += 512) {
        int q = i/NCH, k = i - q*NCH;
        int r = 2+q, cb = 4 + 4*k;
        HWIN(r, cb, o0, o1, o2, o3)
        float4 t = F4(sT,r,cb);
        unsigned m = (t.x==o0 ? 1u:0u) | (t.y==o1 ? 0x100u:0u)
                   | (t.z==o2 ? 0x10000u:0u) | (t.w==o3 ? 0x1000000u:0u);
        U32W(M,r,cb) = m;
    }
    __syncthreads();

#define SUPP(R0, NR)                                                          \
    for (int i = tid; i < (NR)*NCH; i += 512) {                               \
        int q = i/NCH, k = i - q*NCH;                                         \
        int r = (R0)+q, cb = 4 + 4*k;                                         \
        unsigned vm = OR5(r, cb-4), vc = OR5(r, cb), vn = OR5(r, cb+4);       \
        unsigned any = vc | __funnelshift_r(vc,vn,8) | __funnelshift_r(vc,vn,16) \
                          | __funnelshift_l(vm,vc,8) | __funnelshift_l(vm,vc,16);\
        U32W(SMK,r,cb) = any;                                                 \
    }

#define VPASS_SS(R0, NR)                                                      \
    for (int i = tid; i < (NR)*NCH; i += 512) {                               \
        int q = i/NCH, k = i - q*NCH;                                         \
        int r = (R0)+q, cb = 4 + 4*k;                                         \
        float4 v = f4max(f4max(ss_ld(sT,SMK,r-2,cb), ss_ld(sT,SMK,r-1,cb)),   \
                         f4max(ss_ld(sT,SMK,r+1,cb), ss_ld(sT,SMK,r+2,cb)));  \
        F4W(TF,r,cb) = f4max(v, ss_ld(sT,SMK,r,cb));                          \
    }

    // ---- stage 2: SMK2, rows [4,48) ----
    SUPP(4, 44)
    __syncthreads();
    // ---- stage 3: TF = vmax5(SS2) rows [6,46); M |= (SS2==hmax)&!SMK2 ----
    VPASS_SS(6, 40)
    __syncthreads();
    for (int i = tid; i < 40*NCH; i += 512) {
        int q = i/NCH, k = i - q*NCH;
        int r = 6+q, cb = 4 + 4*k;
        HWIN(r, cb, o0, o1, o2, o3)
        float4 ssv = ss_ld(sT, SMK, r, cb);
        unsigned sm = U32(SMK,r,cb);
        unsigned add = 0;
        if (ssv.x==o0 && !(sm & 0xFFu))       add |= 1u;
        if (ssv.y==o1 && !(sm & 0xFF00u))     add |= 0x100u;
        if (ssv.z==o2 && !(sm & 0xFF0000u))   add |= 0x10000u;
        if (ssv.w==o3 && !(sm & 0xFF000000u)) add |= 0x1000000u;
        if (add) U32W(M,r,cb) = U32(M,r,cb) | add;
    }
    __syncthreads();
    // ---- stage 4: SMK4, rows [8,44) ----
    SUPP(8, 36)
    __syncthreads();
    // ---- stage 5: TF = vmax5(SS4) rows [10,42) ----
    VPASS_SS(10, 32)
    __syncthreads();
    // ---- final: rows [10,42), output cols sc [14,78) ----
    for (int i = tid; i < 32*17; i += 512) {
        int q = i/17, k = i - q*17;
        int r = 10+q, cb = 12 + 4*k;
        HWIN(r, cb, o0, o1, o2, o3)
        float4 ssv = ss_ld(sT, SMK, r, cb);
        unsigned sm = U32(SMK,r,cb);
        unsigned mm = U32(M,r,cb);
        float om[4] = {o0, o1, o2, o3};
        float sv[4] = {ssv.x, ssv.y, ssv.z, ssv.w};
        #pragma unroll
        for (int j = 0; j < 4; j++) {
            int sc = cb + j;
            if (sc < 14 || sc >= 78) continue;
            int fin = ((mm >> (8*j)) & 0xFFu)
                    | ((sv[j] == om[j]) && !((sm >> (8*j)) & 0xFFu));
            if (fin) {
                int gy = gy0 + r, gx = gx0 + sc - 4;
                if (gy >= 3 && gy < H-2 && gx >= 3 && gx < W-2) {
                    int pos = atomicAdd(&g_cnt[b], 1);
                    if (pos < CAP) {
                        g_cval[b*CAP + pos] = sT[r*PW + sc];
                        g_cidx[b*CAP + pos] = gy*W + gx;
                    }
                }
            }
        }
    }
}

// ============================================================================
// per-batch top-500: 3-level radix threshold + rank placement; re-zeroes g_cnt
// ============================================================================
__global__ __launch_bounds__(1024) void select_kernel() {
    __shared__ unsigned hist[2048];
    __shared__ unsigned gsum[64];
    __shared__ unsigned sel_key[1024];
    __shared__ int      sel_idx[1024];
    __shared__ int s_bsel, s_need, s_cnt;

    int b = blockIdx.x, tid = threadIdx.x;
    int lane = tid & 31, wid = tid >> 5;
    int n = min(g_cnt[b], CAP);
    __syncthreads();                     // all reads of g_cnt[b] complete ...
    if (tid == 0) g_cnt[b] = 0;          // ... before the reset (replay-safe)
    const float* vals = g_cval + b*CAP;
    const int*   idxs = g_cidx + b*CAP;

    unsigned prefix = 0;
    int need = TOPK;
    for (int level = 0; level < 3; level++) {
        int nbins = (level == 2) ? 1024 : 2048;
        for (int i = tid; i < nbins; i += 1024) hist[i] = 0;
        __syncthreads();
        for (int i = tid; i < n; i += 1024) {
            unsigned key = __float_as_uint(vals[i]);
            unsigned bin; bool ok;
            if (level == 0)      { ok = true;                  bin = key >> 21; }
            else if (level == 1) { ok = (key >> 21) == prefix; bin = (key >> 10) & 0x7FF; }
            else                 { ok = (key >> 10) == prefix; bin = key & 0x3FF; }
            if (ok) atomicAdd(&hist[bin], 1);
        }
        __syncthreads();
        {
            unsigned v = hist[tid];
            #pragma unroll
            for (int o = 16; o > 0; o >>= 1) v += __shfl_down_sync(~0u, v, o);
            if (lane == 0) gsum[wid] = v;
            if (nbins == 2048) {
                unsigned v2 = hist[tid + 1024];
                #pragma unroll
                for (int o = 16; o > 0; o >>= 1) v2 += __shfl_down_sync(~0u, v2, o);
                if (lane == 0) gsum[32 + wid] = v2;
            }
        }
        __syncthreads();
        if (wid == 0) {
            int ng = nbins >> 5;
            unsigned g0 = gsum[lane];
            unsigned g1 = (ng == 64) ? gsum[32 + lane] : 0u;
            unsigned s1 = g1;
            #pragma unroll
            for (int o = 1; o < 32; o <<= 1) { unsigned t = __shfl_down_sync(~0u, s1, o); if (lane + o < 32) s1 += t; }
            unsigned tot1 = __shfl_sync(~0u, s1, 0);
            unsigned s0 = g0;
            #pragma unroll
            for (int o = 1; o < 32; o <<= 1) { unsigned t = __shfl_down_sync(~0u, s0, o); if (lane + o < 32) s0 += t; }
            s0 += tot1;
            unsigned b0 = __ballot_sync(~0u, s0 >= (unsigned)need);
            unsigned b1 = __ballot_sync(~0u, (ng == 64) && (s1 >= (unsigned)need));
            int gstar; unsigned suf_after;
            if (b1) {
                int j = 31 - __clz(b1);
                gstar = 32 + j;
                suf_after = (j == 31) ? 0u : __shfl_sync(~0u, s1, j + 1);
            } else {
                gstar = 31 - __clz(b0);
                suf_after = (gstar == 31) ? tot1 : __shfl_sync(~0u, s0, gstar + 1);
            }
            int need_g = need - (int)suf_after;
            unsigned hs = hist[gstar*32 + lane];
            #pragma unroll
            for (int o = 1; o < 32; o <<= 1) { unsigned t = __shfl_down_sync(~0u, hs, o); if (lane + o < 32) hs += t; }
            unsigned bb = __ballot_sync(~0u, hs >= (unsigned)need_g);
            int bstar = 31 - __clz(bb);
            unsigned bsuf = (bstar == 31) ? 0u : __shfl_sync(~0u, hs, bstar + 1);
            if (lane == 0) { s_bsel = gstar*32 + bstar; s_need = need_g - (int)bsuf; }
        }
        __syncthreads();
        if (level == 0)      prefix = (unsigned)s_bsel;
        else if (level == 1) prefix = (prefix << 11) | (unsigned)s_bsel;
        else                 prefix = (prefix << 10) | (unsigned)s_bsel;
        need = s_need;
        __syncthreads();
    }
    unsigned T = prefix;

    if (tid == 0) s_cnt = 0;
    __syncthreads();
    for (int i = tid; i < n; i += 1024) {
        unsigned key = __float_as_uint(vals[i]);
        if (key >= T) {
            int p = atomicAdd(&s_cnt, 1);
            if (p < 1024) { sel_key[p] = key; sel_idx[p] = idxs[i]; }
        }
    }
    __syncthreads();
    int cnt = min(s_cnt, 1024);
    if (tid < cnt) {
        unsigned ki = sel_key[tid];
        int ii = sel_idx[tid];
        int rank = 0;
        for (int j = 0; j < cnt; j++) {
            unsigned kj = sel_key[j];
            int ij = sel_idx[j];
            rank += (kj > ki) || (kj == ki && ij < ii);
        }
        if (rank < TOPK) g_topk[b*TOPK + rank] = ii;
    }
}

__device__ __forceinline__ float wmax(float v) {
    #pragma unroll
    for (int o = 16; o > 0; o >>= 1) v = fmaxf(v, __shfl_xor_sync(0xffffffffu, v, o));
    return v;
}

// ============================================================================
// fused patch refinement + descriptor sampling: 8 keypoints per 512-thr block
// ============================================================================
__global__ __launch_bounds__(512) void patch_desc_kernel(
        const float* __restrict__ s, const float* __restrict__ dmap,
        float* __restrict__ out) {
    __shared__ float spx[8], spy[8];
    __shared__ float part[16];
    int tid = threadIdx.x;
    int kbase = blockIdx.x * 8;
    int wid = tid >> 5, lane = tid & 31;

    // ---- phase 1: warps 0..7 each refine one keypoint ----
    if (wid < 8) {
        int gw = kbase + wid;
        int b = gw / TOPK;
        int p = g_topk[gw];
        int y = p / W, x = p - y*W;
        int ky = lane / 5, kx = lane - ky*5;
        float v = -FLT_MAX;
        if (lane < 25) v = s[(size_t)b*HW + (y + ky - 2)*W + (x + kx - 2)];
        float mx = wmax(v);
        float gxk = (float)(kx - 2), gyk = (float)(ky - 2);
        float e = (lane < 25) ? __expf((v - mx) * 10.f) : 0.f;
        float s0 = e, s1 = e*gxk, s2 = e*gyk, s3 = e*(gxk*gxk + gyk*gyk);
        #pragma unroll
        for (int o = 16; o > 0; o >>= 1) {
            s0 += __shfl_xor_sync(~0u, s0, o);
            s1 += __shfl_xor_sync(~0u, s1, o);
            s2 += __shfl_xor_sync(~0u, s2, o);
            s3 += __shfl_xor_sync(~0u, s3, o);
        }
        if (lane == 0) {
            float denom = s0 + 1e-12f;
            float inv = 1.f / denom;
            float xr = s1 * inv, yr = s2 * inv;
            float disp = (s3 - 2.f*xr*s1 - 2.f*yr*s2 + (xr*xr + yr*yr)*s0) * 0.25f * inv;
            float fx = (float)x + xr, fy = (float)y + yr;
            float gx = fx / (float)(W-1) * 2.f - 1.f;
            float gy = fy / (float)(H-1) * 2.f - 1.f;
            out[KXY_OFF + gw*2 + 0] = gx;
            out[KXY_OFF + gw*2 + 1] = gy;
            out[DISP_OFF + gw] = disp;

            float px = fminf(fmaxf((gx + 1.f) * 0.5f * (float)(W-1), 0.f), (float)(W-1));
            float py = fminf(fmaxf((gy + 1.f) * 0.5f * (float)(H-1), 0.f), (float)(H-1));
            spx[wid] = px; spy[wid] = py;
            int x0 = (int)floorf(px), y0 = (int)floorf(py);
            float wx = px - (float)x0, wy = py - (float)y0;
            int x1 = min(x0 + 1, W-1), y1 = min(y0 + 1, H-1);
            const float* sb = s + (size_t)b*HW;
            float v00 = sb[y0*W + x0], v01 = sb[y0*W + x1];
            float v10 = sb[y1*W + x0], v11 = sb[y1*W + x1];
            out[KPS_OFF + gw] = v00*(1.f-wx)*(1.f-wy) + v01*wx*(1.f-wy)
                              + v10*(1.f-wx)*wy       + v11*wx*wy;
        }
    }
    __syncthreads();

    // ---- phase 2: descriptor gather + L2 norm (64 threads / keypoint) ----
    int kl = tid >> 6;            // 0..7
    int c  = tid & 63;
    int g  = kbase + kl;
    int b  = g / TOPK;
    float px = spx[kl], py = spy[kl];
    int x0 = (int)floorf(px), y0 = (int)floorf(py);
    float wx = px - (float)x0, wy = py - (float)y0;
    int x1 = min(x0 + 1, W-1), y1 = min(y0 + 1, H-1);
    const float* base = dmap + ((size_t)b*64 + c) * (size_t)HW;
    float v00 = base[y0*W + x0], v01 = base[y0*W + x1];
    float v10 = base[y1*W + x0], v11 = base[y1*W + x1];
    float d = v00*(1.f-wx)*(1.f-wy) + v01*wx*(1.f-wy)
            + v10*(1.f-wx)*wy       + v11*wx*wy;

    float ss = d * d;
    #pragma unroll
    for (int o = 16; o > 0; o >>= 1) ss += __shfl_xor_sync(0xffffffffu, ss, o);
    if (lane == 0) part[wid] = ss;
    __syncthreads();
    float tot = part[2*kl] + part[2*kl + 1];
    float nrm = fmaxf(sqrtf(tot), 1e-12f);
    out[DESC_OFF + g*64 + c] = d / nrm;
}

extern "C" void kernel_launch(void* const* d_in, const int* in_sizes, int n_in,
                              void* d_out, int out_size) {
    const float* scores = (const float*)d_in[0];
    const float* descs  = (const float*)d_in[1];
    float* out = (float*)d_out;

    nms_kernel<<<dim3(W/64, H/32, B), 512>>>(scores);
    select_kernel<<<B, 1024>>>();
    patch_desc_kernel<<<NKP/8, 512>>>(scores, descs, out);
}